// round 1
// baseline (speedup 1.0000x reference)
#include <cuda_runtime.h>
#include <cuda_bf16.h>

#define N_READS   1048576
#define G_TOTAL   32768
#define M_GROUP   32
#define DIMX      16
#define DIMIN     18
#define H1        150
#define PP        8
#define AGG_DIM   40

// ---------------------------------------------------------------------------
// Fully fused kernel:
//   per-read MLP (18->150 relu ->8 relu), warp-level group aggregation
//   (mean/var/min/median/max over 32 reads), group MLP (40->150 relu ->1
//   sigmoid). One warp handles 2 groups (lane = read-within-group) so each
//   broadcast LDS of a weight feeds two FFMAs.
// ---------------------------------------------------------------------------

__device__ __forceinline__ float group_tail(const float a[PP],
                                            const float* __restrict__ W3s,
                                            const float* __restrict__ b3s,
                                            const float* __restrict__ W4s,
                                            float b4v, int lane)
{
    float agg[AGG_DIM];

    #pragma unroll
    for (int p = 0; p < PP; ++p) {
        float v = a[p];

        // mean
        float s = v;
        #pragma unroll
        for (int o = 16; o; o >>= 1) s += __shfl_xor_sync(0xffffffffu, s, o);
        float mean = s * (1.0f / 32.0f);

        // unbiased variance (two-pass: exact vs reference formula)
        float d = v - mean;
        float sq = d * d;
        #pragma unroll
        for (int o = 16; o; o >>= 1) sq += __shfl_xor_sync(0xffffffffu, sq, o);
        float var = sq * (1.0f / 31.0f);

        // min / max
        float mn = v, mx = v;
        #pragma unroll
        for (int o = 16; o; o >>= 1) {
            mn = fminf(mn, __shfl_xor_sync(0xffffffffu, mn, o));
            mx = fmaxf(mx, __shfl_xor_sync(0xffffffffu, mx, o));
        }

        // lower median: bitonic sort across the warp, take sorted[15]
        float t = v;
        #pragma unroll
        for (int k = 2; k <= 32; k <<= 1) {
            #pragma unroll
            for (int j = k >> 1; j > 0; j >>= 1) {
                float o2 = __shfl_xor_sync(0xffffffffu, t, j);
                bool lower = ((lane & j) == 0);
                bool asc   = ((lane & k) == 0);   // k==32: lane&32==0 always
                float lo = fminf(t, o2), hi = fmaxf(t, o2);
                t = (asc == lower) ? lo : hi;
            }
        }
        float med = __shfl_sync(0xffffffffu, t, 15);

        agg[0 * PP + p] = mean;
        agg[1 * PP + p] = var;
        agg[2 * PP + p] = mn;
        agg[3 * PP + p] = med;
        agg[4 * PP + p] = mx;
    }

    // MLP3 (40->150, relu) + MLP4 (150->1): hidden units strided across lanes
    float zp = 0.0f;
    #pragma unroll 1
    for (int j = lane; j < H1; j += 32) {
        float t = b3s[j];
        #pragma unroll
        for (int k = 0; k < AGG_DIM; ++k)
            t = fmaf(agg[k], W3s[k * H1 + j], t);
        t = fmaxf(t, 0.0f);
        zp = fmaf(t, W4s[j], zp);
    }
    #pragma unroll
    for (int o = 16; o; o >>= 1) zp += __shfl_xor_sync(0xffffffffu, zp, o);

    return 1.0f / (1.0f + __expf(-(zp + b4v)));
}

__global__ void __launch_bounds__(256, 2)
minn_fused_kernel(const float* __restrict__ x,
                  const int*   __restrict__ kmer,
                  const int*   __restrict__ indices,
                  const float* __restrict__ emb,
                  const float* __restrict__ W1, const float* __restrict__ b1,
                  const float* __restrict__ W2, const float* __restrict__ b2,
                  const float* __restrict__ W3, const float* __restrict__ b3,
                  const float* __restrict__ W4, const float* __restrict__ b4,
                  float* __restrict__ out)
{
    __shared__ float W1s[DIMIN * H1];   // 2700 floats
    __shared__ float b1s[H1];
    __shared__ float W2s[H1 * PP];      // 1200 floats
    __shared__ float b2s[PP];
    __shared__ float W3s[AGG_DIM * H1]; // 6000 floats
    __shared__ float b3s[H1];
    __shared__ float W4s[H1];

    const int tid = threadIdx.x;

    for (int i = tid; i < DIMIN * H1; i += 256) W1s[i] = W1[i];
    for (int i = tid; i < H1 * PP;   i += 256) W2s[i] = W2[i];
    for (int i = tid; i < AGG_DIM * H1; i += 256) W3s[i] = W3[i];
    for (int i = tid; i < H1; i += 256) {
        b1s[i] = b1[i];
        b3s[i] = b3[i];
        W4s[i] = W4[i];
    }
    if (tid < PP) b2s[tid] = b2[tid];
    const float b4v = __ldg(b4);
    __syncthreads();

    const int warp = tid >> 5;
    const int lane = tid & 31;
    const int gbase = (blockIdx.x * 8 + warp) * 2;   // 2 groups per warp
    if (gbase >= G_TOTAL) return;

    // ---- load the two reads this lane owns (one per group) ----
    const int r0 = indices[gbase * M_GROUP + lane];
    const int r1 = indices[(gbase + 1) * M_GROUP + lane];

    float in0[DIMIN], in1[DIMIN];
    {
        const float4* p0 = (const float4*)(x + (size_t)r0 * DIMX);
        const float4* p1 = (const float4*)(x + (size_t)r1 * DIMX);
        #pragma unroll
        for (int q = 0; q < 4; ++q) {
            float4 v0 = p0[q], v1 = p1[q];
            in0[q * 4 + 0] = v0.x; in0[q * 4 + 1] = v0.y;
            in0[q * 4 + 2] = v0.z; in0[q * 4 + 3] = v0.w;
            in1[q * 4 + 0] = v1.x; in1[q * 4 + 1] = v1.y;
            in1[q * 4 + 2] = v1.z; in1[q * 4 + 3] = v1.w;
        }
        const int k0 = kmer[r0], k1 = kmer[r1];
        in0[16] = __ldg(emb + k0 * 2);     in0[17] = __ldg(emb + k0 * 2 + 1);
        in1[16] = __ldg(emb + k1 * 2);     in1[17] = __ldg(emb + k1 * 2 + 1);
    }

    // ---- per-read MLP: 18 -> 150 (relu) -> 8 (relu), both reads fused ----
    float a0[PP], a1[PP];
    #pragma unroll
    for (int p = 0; p < PP; ++p) { a0[p] = b2s[p]; a1[p] = b2s[p]; }

    #pragma unroll 2
    for (int j = 0; j < H1; ++j) {
        float h0 = b1s[j];
        float h1 = h0;
        #pragma unroll
        for (int k = 0; k < DIMIN; ++k) {
            float w = W1s[k * H1 + j];
            h0 = fmaf(in0[k], w, h0);
            h1 = fmaf(in1[k], w, h1);
        }
        h0 = fmaxf(h0, 0.0f);
        h1 = fmaxf(h1, 0.0f);
        #pragma unroll
        for (int p = 0; p < PP; ++p) {
            float w2 = W2s[j * PP + p];
            a0[p] = fmaf(h0, w2, a0[p]);
            a1[p] = fmaf(h1, w2, a1[p]);
        }
    }
    #pragma unroll
    for (int p = 0; p < PP; ++p) {
        a0[p] = fmaxf(a0[p], 0.0f);
        a1[p] = fmaxf(a1[p], 0.0f);
    }

    // ---- group aggregation + group MLP, one group at a time ----
    float o0 = group_tail(a0, W3s, b3s, W4s, b4v, lane);
    if (lane == 0) out[gbase] = o0;
    float o1 = group_tail(a1, W3s, b3s, W4s, b4v, lane);
    if (lane == 0) out[gbase + 1] = o1;
}

extern "C" void kernel_launch(void* const* d_in, const int* in_sizes, int n_in,
                              void* d_out, int out_size)
{
    const float* x       = (const float*)d_in[0];
    const int*   kmer    = (const int*)  d_in[1];
    const int*   indices = (const int*)  d_in[2];
    const float* emb     = (const float*)d_in[3];
    const float* W1      = (const float*)d_in[4];
    const float* b1      = (const float*)d_in[5];
    const float* W2      = (const float*)d_in[6];
    const float* b2      = (const float*)d_in[7];
    const float* W3      = (const float*)d_in[8];
    const float* b3      = (const float*)d_in[9];
    const float* W4      = (const float*)d_in[10];
    const float* b4      = (const float*)d_in[11];
    float* out = (float*)d_out;

    // 8 warps/block, 2 groups/warp -> 16 groups/block
    const int blocks = G_TOTAL / 16;   // 2048
    minn_fused_kernel<<<blocks, 256>>>(x, kmer, indices, emb,
                                       W1, b1, W2, b2, W3, b3, W4, b4, out);
}